// round 1
// baseline (speedup 1.0000x reference)
#include <cuda_runtime.h>
#include <cstdint>

#define N_NODES 100000
#define N_EDGES 1600000
#define N_GRAPHS 512
#define FDIM 128

// ---------------- device scratch (allocation-free: __device__ globals) ------
__device__ float    g_h[(size_t)N_NODES * FDIM];     // post-GEMM features
__device__ float    g_agg[(size_t)N_NODES * FDIM];   // post-aggregation features
__device__ int      g_deg[N_NODES];
__device__ int      g_cursor[N_NODES];
__device__ float    g_dinv[N_NODES];
__device__ int      g_rowoff[N_NODES + 1];
__device__ int      g_esrc[N_EDGES];
__device__ float    g_enorm[N_EDGES];
__device__ float    g_sums[N_GRAPHS * FDIM];
__device__ unsigned g_maxenc[N_GRAPHS * FDIM];
__device__ int      g_cnt[N_GRAPHS];

// ---------------- helpers ---------------------------------------------------
__device__ __forceinline__ unsigned enc_max(float f) {
    unsigned u = __float_as_uint(f);
    return (u & 0x80000000u) ? ~u : (u | 0x80000000u);
}
__device__ __forceinline__ float dec_max(unsigned e) {
    unsigned bits = (e & 0x80000000u) ? (e ^ 0x80000000u) : ~e;
    return __uint_as_float(bits);
}

// ---------------- preprocessing ---------------------------------------------
__global__ void zero_kernel() {
    int i = blockIdx.x * blockDim.x + threadIdx.x;
    if (i < N_NODES) { g_deg[i] = 0; g_cursor[i] = 0; }
    if (i < N_GRAPHS * FDIM) { g_sums[i] = 0.0f; g_maxenc[i] = 0u; }
    if (i < N_GRAPHS) g_cnt[i] = 0;
}

__global__ void hist_kernel(const int* __restrict__ dst) {
    int stride = gridDim.x * blockDim.x;
    for (int e = blockIdx.x * blockDim.x + threadIdx.x; e < N_EDGES; e += stride)
        atomicAdd(&g_deg[dst[e]], 1);
}

__global__ void dinv_kernel() {
    int i = blockIdx.x * blockDim.x + threadIdx.x;
    if (i < N_NODES) g_dinv[i] = rsqrtf((float)g_deg[i] + 1.0f);
}

// single-block exclusive scan of g_deg -> g_rowoff (N = 100000, 1024 threads)
__global__ void scan_kernel() {
    __shared__ int s[1024];
    int t = threadIdx.x;
    const int CH = (N_NODES + 1023) / 1024;  // 98
    int beg = t * CH;
    int end = min(beg + CH, N_NODES);
    int sum = 0;
    for (int i = beg; i < end; i++) sum += g_deg[i];
    s[t] = sum;
    __syncthreads();
    for (int off = 1; off < 1024; off <<= 1) {
        int v = (t >= off) ? s[t - off] : 0;
        __syncthreads();
        s[t] += v;
        __syncthreads();
    }
    int run = (t == 0) ? 0 : s[t - 1];
    for (int i = beg; i < end; i++) { g_rowoff[i] = run; run += g_deg[i]; }
    if (t == 1023) g_rowoff[N_NODES] = s[1023];
}

__global__ void scatter_kernel(const int* __restrict__ src, const int* __restrict__ dst) {
    int stride = gridDim.x * blockDim.x;
    for (int e = blockIdx.x * blockDim.x + threadIdx.x; e < N_EDGES; e += stride) {
        int s = src[e], d = dst[e];
        int pos = g_rowoff[d] + atomicAdd(&g_cursor[d], 1);
        g_esrc[pos] = s;
        g_enorm[pos] = g_dinv[s] * g_dinv[d];
    }
}

// ---------------- dense GEMM: out[N,128] = act(A[N,128]) @ W[128,128] -------
template <bool RELU_IN>
__global__ void gemm128(const float* __restrict__ A, const float* __restrict__ W,
                        float* __restrict__ out) {
    __shared__ float As[32 * 128];
    __shared__ float Ws[32 * 128];
    int tid = threadIdx.x;            // 256 threads
    int row0 = blockIdx.x * 32;

    // load A tile (32 rows x 128)
    const float4* A4 = (const float4*)(A + (size_t)row0 * FDIM);
    float4* As4 = (float4*)As;
#pragma unroll
    for (int i = 0; i < 4; i++) {
        float4 v = A4[tid + i * 256];
        if (RELU_IN) {
            v.x = fmaxf(v.x, 0.0f); v.y = fmaxf(v.y, 0.0f);
            v.z = fmaxf(v.z, 0.0f); v.w = fmaxf(v.w, 0.0f);
        }
        As4[tid + i * 256] = v;
    }

    int warp = tid >> 5, lane = tid & 31;
    float4 acc[4];
#pragma unroll
    for (int r = 0; r < 4; r++) acc[r] = make_float4(0.f, 0.f, 0.f, 0.f);

    for (int kb = 0; kb < 4; kb++) {
        __syncthreads();
        const float4* W4 = (const float4*)(W + (size_t)kb * 32 * FDIM);
        float4* Ws4 = (float4*)Ws;
#pragma unroll
        for (int i = 0; i < 4; i++) Ws4[tid + i * 256] = W4[tid + i * 256];
        __syncthreads();
#pragma unroll
        for (int k = 0; k < 32; k++) {
            float4 w = ((const float4*)Ws)[k * 32 + lane];
#pragma unroll
            for (int r = 0; r < 4; r++) {
                float a = As[(warp * 4 + r) * FDIM + kb * 32 + k];
                acc[r].x += a * w.x; acc[r].y += a * w.y;
                acc[r].z += a * w.z; acc[r].w += a * w.w;
            }
        }
    }
#pragma unroll
    for (int r = 0; r < 4; r++) {
        int row = row0 + warp * 4 + r;
        ((float4*)(out + (size_t)row * FDIM))[lane] = acc[r];
    }
}

// ---------------- aggregation: one warp per dst node (no atomics) -----------
__global__ void agg_kernel(const float* __restrict__ h, const float* __restrict__ bias,
                           float* __restrict__ out) {
    int warp = (blockIdx.x * blockDim.x + threadIdx.x) >> 5;
    int lane = threadIdx.x & 31;
    if (warp >= N_NODES) return;
    int node = warp;

    float di = g_dinv[node];
    float sc = di * di;
    float4 b4 = ((const float4*)bias)[lane];
    float4 hv = ((const float4*)(h + (size_t)node * FDIM))[lane];
    float4 acc;
    acc.x = b4.x + hv.x * sc; acc.y = b4.y + hv.y * sc;
    acc.z = b4.z + hv.z * sc; acc.w = b4.w + hv.w * sc;

    int beg = g_rowoff[node], end = g_rowoff[node + 1];
    for (int i = beg; i < end; i++) {
        int s = g_esrc[i];
        float w = g_enorm[i];
        float4 v = __ldg((const float4*)(h + (size_t)s * FDIM) + lane);
        acc.x += w * v.x; acc.y += w * v.y; acc.z += w * v.z; acc.w += w * v.w;
    }
    ((float4*)(out + (size_t)node * FDIM))[lane] = acc;
}

// ---------------- pooling: warp handles 32 consecutive nodes (sorted batch) -
__global__ void pool_kernel(const int* __restrict__ batch) {
    int warp = (blockIdx.x * blockDim.x + threadIdx.x) >> 5;
    int lane = threadIdx.x & 31;
    int beg = warp * 32;
    if (beg >= N_NODES) return;
    int end = min(beg + 32, N_NODES);

    int cur = batch[beg];
    float4 s = make_float4(0.f, 0.f, 0.f, 0.f);
    float4 m = make_float4(-INFINITY, -INFINITY, -INFINITY, -INFINITY);
    int cnt = 0;

    for (int node = beg; node < end; node++) {
        int b = batch[node];
        if (b != cur) {
            int base = cur * FDIM + lane * 4;
            atomicAdd(&g_sums[base + 0], s.x); atomicAdd(&g_sums[base + 1], s.y);
            atomicAdd(&g_sums[base + 2], s.z); atomicAdd(&g_sums[base + 3], s.w);
            atomicMax(&g_maxenc[base + 0], enc_max(m.x));
            atomicMax(&g_maxenc[base + 1], enc_max(m.y));
            atomicMax(&g_maxenc[base + 2], enc_max(m.z));
            atomicMax(&g_maxenc[base + 3], enc_max(m.w));
            if (lane == 0) atomicAdd(&g_cnt[cur], cnt);
            s = make_float4(0.f, 0.f, 0.f, 0.f);
            m = make_float4(-INFINITY, -INFINITY, -INFINITY, -INFINITY);
            cnt = 0;
            cur = b;
        }
        float4 v = ((const float4*)(g_agg + (size_t)node * FDIM))[lane];
        s.x += v.x; s.y += v.y; s.z += v.z; s.w += v.w;
        m.x = fmaxf(m.x, v.x); m.y = fmaxf(m.y, v.y);
        m.z = fmaxf(m.z, v.z); m.w = fmaxf(m.w, v.w);
        cnt++;
    }
    int base = cur * FDIM + lane * 4;
    atomicAdd(&g_sums[base + 0], s.x); atomicAdd(&g_sums[base + 1], s.y);
    atomicAdd(&g_sums[base + 2], s.z); atomicAdd(&g_sums[base + 3], s.w);
    atomicMax(&g_maxenc[base + 0], enc_max(m.x));
    atomicMax(&g_maxenc[base + 1], enc_max(m.y));
    atomicMax(&g_maxenc[base + 2], enc_max(m.z));
    atomicMax(&g_maxenc[base + 3], enc_max(m.w));
    if (lane == 0) atomicAdd(&g_cnt[cur], cnt);
}

// ---------------- classifier head: one block per graph ----------------------
__global__ void classifier_kernel(const float* __restrict__ Wc1, const float* __restrict__ bc1,
                                  const float* __restrict__ Wc2, const float* __restrict__ bc2,
                                  float* __restrict__ out) {
    int g = blockIdx.x, t = threadIdx.x;  // 128 threads
    __shared__ float gv[256];
    __shared__ float hs[128];

    int cnt = g_cnt[g];
    float inv = 1.0f / (float)max(cnt, 1);
    gv[t] = g_sums[g * FDIM + t] * inv;
    unsigned e = g_maxenc[g * FDIM + t];
    gv[128 + t] = (cnt == 0) ? 0.0f : dec_max(e);
    __syncthreads();

    float acc = bc1[t];
#pragma unroll 8
    for (int k = 0; k < 256; k++) acc += gv[k] * Wc1[k * 128 + t];
    hs[t] = fmaxf(acc, 0.0f);
    __syncthreads();

    if (t < 10) {
        float o = bc2[t];
#pragma unroll 8
        for (int k = 0; k < 128; k++) o += hs[k] * Wc2[k * 10 + t];
        out[g * 10 + t] = o;
    }
}

// ---------------- launch -----------------------------------------------------
extern "C" void kernel_launch(void* const* d_in, const int* in_sizes, int n_in,
                              void* d_out, int out_size) {
    const float* x    = (const float*)d_in[0];
    const int*   ei   = (const int*)d_in[1];
    const int*   src  = ei;
    const int*   dst  = ei + N_EDGES;
    const int*   batch = (const int*)d_in[2];
    const float* W1 = (const float*)d_in[3];  const float* b1 = (const float*)d_in[4];
    const float* W2 = (const float*)d_in[5];  const float* b2 = (const float*)d_in[6];
    const float* W3 = (const float*)d_in[7];  const float* b3 = (const float*)d_in[8];
    const float* Wc1 = (const float*)d_in[9]; const float* bc1 = (const float*)d_in[10];
    const float* Wc2 = (const float*)d_in[11]; const float* bc2 = (const float*)d_in[12];
    float* out = (float*)d_out;

    // preprocessing: degrees, CSR-by-dst with precomputed edge norms
    zero_kernel<<<(N_NODES + 255) / 256, 256>>>();
    hist_kernel<<<2048, 256>>>(dst);
    dinv_kernel<<<(N_NODES + 255) / 256, 256>>>();
    scan_kernel<<<1, 1024>>>();
    scatter_kernel<<<2048, 256>>>(src, dst);

    float* d_h;  cudaGetSymbolAddress((void**)&d_h, g_h);
    float* d_a;  cudaGetSymbolAddress((void**)&d_a, g_agg);

    const int GEMM_BLOCKS = N_NODES / 32;       // 3125
    const int AGG_BLOCKS  = (N_NODES * 32 + 255) / 256;  // 12500

    // layer 1: h = x @ W1 ; agg = scatter + self + b1
    gemm128<false><<<GEMM_BLOCKS, 256>>>(x, W1, d_h);
    agg_kernel<<<AGG_BLOCKS, 256>>>(d_h, b1, d_a);
    // layer 2: h = relu(agg) @ W2
    gemm128<true><<<GEMM_BLOCKS, 256>>>(d_a, W2, d_h);
    agg_kernel<<<AGG_BLOCKS, 256>>>(d_h, b2, d_a);
    // layer 3: h = relu(agg) @ W3 (no relu after)
    gemm128<true><<<GEMM_BLOCKS, 256>>>(d_a, W3, d_h);
    agg_kernel<<<AGG_BLOCKS, 256>>>(d_h, b3, d_a);

    // pooling + head
    int pool_warps = (N_NODES + 31) / 32;       // 3125
    pool_kernel<<<(pool_warps * 32 + 255) / 256, 256>>>(batch);
    classifier_kernel<<<N_GRAPHS, 128>>>(Wc1, bc1, Wc2, bc2, out);
}